// round 5
// baseline (speedup 1.0000x reference)
#include <cuda_runtime.h>
#include <math.h>

#define N_NODES 128
#define F_DIM   128
#define H_DIM   64
#define C_OUT   40
#define BATCH   4096

#define A2_STRIDE 132   // padded row stride (132 % 32 == 4) for conflict-free access
#define X_STRIDE  132
#define Y_STRIDE  68

__device__ __align__(16) float g_Ahat[N_NODES * N_NODES];   // A_sym + I (unnormalized)
__device__ __align__(16) float g_deg[N_NODES];
__device__ __align__(16) float g_A2[N_NODES * A2_STRIDE];   // (D^-1/2 Ahat D^-1/2)^2, padded

typedef unsigned long long u64;

__device__ __forceinline__ u64 pk2(float a, float b) {
    u64 r; asm("mov.b64 %0, {%1, %2};" : "=l"(r) : "f"(a), "f"(b)); return r;
}
__device__ __forceinline__ u64 ffma2(u64 a, u64 b, u64 c) {
    u64 d; asm("fma.rn.f32x2 %0, %1, %2, %3;" : "=l"(d) : "l"(a), "l"(b), "l"(c)); return d;
}
__device__ __forceinline__ float2 up2(u64 v) {
    float lo, hi; asm("mov.b64 {%0, %1}, %2;" : "=f"(lo), "=f"(hi) : "l"(v));
    return make_float2(lo, hi);
}

// ---------------------------------------------------------------------------
// Kernel 1: build Ahat = A_sym + I and row degrees. Grid(128) x 128 threads:
// block = row i, thread = col j. Block-reduce degree.
// ---------------------------------------------------------------------------
__global__ void build_Ahat(const float* __restrict__ edge_w) {
    __shared__ float red[4];
    int i = blockIdx.x, j = threadIdx.x;
    int a = i > j ? i : j;
    int b = i > j ? j : i;
    float v = edge_w[(a * (a + 1)) / 2 + b];   // tril row-major index
    if (i == j) v += 1.0f;                     // self loop
    g_Ahat[i * N_NODES + j] = v;
    // block reduce (4 warps)
    float s = v;
#pragma unroll
    for (int o = 16; o > 0; o >>= 1) s += __shfl_xor_sync(0xffffffffu, s, o);
    if ((j & 31) == 0) red[j >> 5] = s;
    __syncthreads();
    if (j == 0) g_deg[i] = red[0] + red[1] + red[2] + red[3];
}

// ---------------------------------------------------------------------------
// Kernel 2: A2 = (D^-1/2 Ahat D^-1/2)^2, folded normalization:
//   A2[i][j] = dinv_i * dinv_j * sum_k Ahat[i,k] * dinv_k^2 * Ahat[k,j]
// Grid(128) x 128 threads. Stored padded stride 132, pad zeroed.
// ---------------------------------------------------------------------------
__global__ void build_A2() {
    __shared__ float rowi[N_NODES];   // Ahat[i,k] * dinv_k^2
    __shared__ float dinvS[N_NODES];
    int i = blockIdx.x, j = threadIdx.x;
    float dg = g_deg[j];
    float dj = (dg > 0.f) ? (1.0f / sqrtf(dg)) : 0.0f;
    dinvS[j] = dj;
    rowi[j] = g_Ahat[i * N_NODES + j] * dj * dj;
    __syncthreads();
    float s = 0.f;
    for (int k = 0; k < N_NODES; k++)
        s = fmaf(rowi[k], g_Ahat[k * N_NODES + j], s);
    g_A2[i * A2_STRIDE + j] = s * dinvS[i] * dinvS[j];
    if (j < A2_STRIDE - N_NODES) g_A2[i * A2_STRIDE + N_NODES + j] = 0.f;
}

// ---------------------------------------------------------------------------
// Kernel 3: fused per-batch pipeline. One batch per CTA, 256 threads,
// 2 CTAs per SM (smem ~102.7KB). Per-CTA data (Xt, Ys) in smem; data shared
// across CTAs (lin_w, g_A2) streamed from global (L2-resident).
//   Y = X @ W ; Z = A2 @ Y ; h = relu(Z + b) ; pooled = relu(conv) ; out = fc
// Thread (ty,tx): ty=tid>>3 (32 x 4 node rows), tx=tid&7 (8 x 8 hidden cols).
// ---------------------------------------------------------------------------
__global__ void __launch_bounds__(256, 2) fused_kernel(
    const float* __restrict__ x,
    const float* __restrict__ lin_w, const float* __restrict__ lin_b,
    const float* __restrict__ conv_w, const float* __restrict__ conv_b,
    const float* __restrict__ fc_w, const float* __restrict__ fc_b,
    float* __restrict__ out)
{
    extern __shared__ float sm[];
    float* Xt  = sm;                          // [128][132]  Xt[f][n] (transposed)
    float* Ys  = Xt + F_DIM * X_STRIDE;       // [128][68]
    float* pooledS = Ys + N_NODES * Y_STRIDE; // [64]

    const int tid = threadIdx.x;
    const int tx = tid & 7;    // h columns 8*tx .. 8*tx+7
    const int ty = tid >> 3;   // n rows    4*ty .. 4*ty+3
    const int b = blockIdx.x;

    if (tid < H_DIM) pooledS[tid] = conv_b[0];

    // --- load X transposed: Xt[f][n] = X[n][f]; lane -> n keeps the 4 scalar
    //     smem stores per float4 bank-conflict-free. ---
    {
        const float4* X4 = (const float4*)(x + (size_t)b * N_NODES * F_DIM);
        for (int idx = tid; idx < N_NODES * F_DIM / 4; idx += 256) {
            int l = idx & 31;
            int g = idx >> 5;
            int n = ((g & 3) << 5) | l;
            int f4 = g >> 2;
            float4 v = X4[n * (F_DIM / 4) + f4];
            int f = f4 * 4;
            Xt[(f + 0) * X_STRIDE + n] = v.x;
            Xt[(f + 1) * X_STRIDE + n] = v.y;
            Xt[(f + 2) * X_STRIDE + n] = v.z;
            Xt[(f + 3) * X_STRIDE + n] = v.w;
        }
    }
    __syncthreads();

    u64 acc[4][4];
#pragma unroll
    for (int i = 0; i < 4; i++)
#pragma unroll
        for (int p = 0; p < 4; p++) acc[i][p] = 0ull;

    // ---------------- GEMM1: Y = X @ W  (W from global / L2) ----------------
    const float* Wp = lin_w + 8 * tx;
#pragma unroll 4
    for (int f = 0; f < F_DIM; f++) {
        float4 xv = *(const float4*)(Xt + f * X_STRIDE + 4 * ty);
        float4 w0 = __ldg((const float4*)(Wp + f * H_DIM));
        float4 w1 = __ldg((const float4*)(Wp + f * H_DIM + 4));
        u64 b0 = pk2(w0.x, w0.y), b1 = pk2(w0.z, w0.w);
        u64 b2 = pk2(w1.x, w1.y), b3 = pk2(w1.z, w1.w);
        u64 a0 = pk2(xv.x, xv.x), a1 = pk2(xv.y, xv.y);
        u64 a2 = pk2(xv.z, xv.z), a3 = pk2(xv.w, xv.w);
        acc[0][0]=ffma2(a0,b0,acc[0][0]); acc[0][1]=ffma2(a0,b1,acc[0][1]);
        acc[0][2]=ffma2(a0,b2,acc[0][2]); acc[0][3]=ffma2(a0,b3,acc[0][3]);
        acc[1][0]=ffma2(a1,b0,acc[1][0]); acc[1][1]=ffma2(a1,b1,acc[1][1]);
        acc[1][2]=ffma2(a1,b2,acc[1][2]); acc[1][3]=ffma2(a1,b3,acc[1][3]);
        acc[2][0]=ffma2(a2,b0,acc[2][0]); acc[2][1]=ffma2(a2,b1,acc[2][1]);
        acc[2][2]=ffma2(a2,b2,acc[2][2]); acc[2][3]=ffma2(a2,b3,acc[2][3]);
        acc[3][0]=ffma2(a3,b0,acc[3][0]); acc[3][1]=ffma2(a3,b1,acc[3][1]);
        acc[3][2]=ffma2(a3,b2,acc[3][2]); acc[3][3]=ffma2(a3,b3,acc[3][3]);
    }

    // store Y tile
#pragma unroll
    for (int i = 0; i < 4; i++) {
        int n = 4 * ty + i;
        float2 z0 = up2(acc[i][0]), z1 = up2(acc[i][1]);
        float2 z2 = up2(acc[i][2]), z3 = up2(acc[i][3]);
        *(float4*)(Ys + n * Y_STRIDE + 8 * tx)     = make_float4(z0.x, z0.y, z1.x, z1.y);
        *(float4*)(Ys + n * Y_STRIDE + 8 * tx + 4) = make_float4(z2.x, z2.y, z3.x, z3.y);
    }
    __syncthreads();

#pragma unroll
    for (int i = 0; i < 4; i++)
#pragma unroll
        for (int p = 0; p < 4; p++) acc[i][p] = 0ull;

    // ---------------- GEMM2: Z = A2 @ Y  (A2 from global / L2) ----------------
    // A2 symmetric: A2[j][n] == A2[n][j], so the float4 over n works directly.
    const float* A2p = g_A2 + 4 * ty;
#pragma unroll 4
    for (int j = 0; j < N_NODES; j++) {
        float4 av = __ldg((const float4*)(A2p + j * A2_STRIDE));
        float4 y0 = *(const float4*)(Ys + j * Y_STRIDE + 8 * tx);
        float4 y1 = *(const float4*)(Ys + j * Y_STRIDE + 8 * tx + 4);
        u64 b0 = pk2(y0.x, y0.y), b1 = pk2(y0.z, y0.w);
        u64 b2 = pk2(y1.x, y1.y), b3 = pk2(y1.z, y1.w);
        u64 a0 = pk2(av.x, av.x), a1 = pk2(av.y, av.y);
        u64 a2 = pk2(av.z, av.z), a3 = pk2(av.w, av.w);
        acc[0][0]=ffma2(a0,b0,acc[0][0]); acc[0][1]=ffma2(a0,b1,acc[0][1]);
        acc[0][2]=ffma2(a0,b2,acc[0][2]); acc[0][3]=ffma2(a0,b3,acc[0][3]);
        acc[1][0]=ffma2(a1,b0,acc[1][0]); acc[1][1]=ffma2(a1,b1,acc[1][1]);
        acc[1][2]=ffma2(a1,b2,acc[1][2]); acc[1][3]=ffma2(a1,b3,acc[1][3]);
        acc[2][0]=ffma2(a2,b0,acc[2][0]); acc[2][1]=ffma2(a2,b1,acc[2][1]);
        acc[2][2]=ffma2(a2,b2,acc[2][2]); acc[2][3]=ffma2(a2,b3,acc[2][3]);
        acc[3][0]=ffma2(a3,b0,acc[3][0]); acc[3][1]=ffma2(a3,b1,acc[3][1]);
        acc[3][2]=ffma2(a3,b2,acc[3][2]); acc[3][3]=ffma2(a3,b3,acc[3][3]);
    }

    // ---------------- epilogue: bias + relu + conv pool ----------------
    float lb[8];
    {
        float4 l0 = __ldg((const float4*)(lin_b + 8 * tx));
        float4 l1 = __ldg((const float4*)(lin_b + 8 * tx + 4));
        lb[0]=l0.x; lb[1]=l0.y; lb[2]=l0.z; lb[3]=l0.w;
        lb[4]=l1.x; lb[5]=l1.y; lb[6]=l1.z; lb[7]=l1.w;
    }
    float pool[8] = {0,0,0,0,0,0,0,0};
#pragma unroll
    for (int i = 0; i < 4; i++) {
        float cw = __ldg(conv_w + 4 * ty + i);
#pragma unroll
        for (int p = 0; p < 4; p++) {
            float2 z = up2(acc[i][p]);
            pool[2*p]   = fmaf(fmaxf(z.x + lb[2*p],   0.f), cw, pool[2*p]);
            pool[2*p+1] = fmaf(fmaxf(z.y + lb[2*p+1], 0.f), cw, pool[2*p+1]);
        }
    }
    // reduce across the 4 ty values sharing a warp (lane bits 3,4), then atomics
#pragma unroll
    for (int jj = 0; jj < 8; jj++) {
        pool[jj] += __shfl_xor_sync(0xffffffffu, pool[jj], 8);
        pool[jj] += __shfl_xor_sync(0xffffffffu, pool[jj], 16);
    }
    if ((tid & 24) == 0) {   // one lane per tx per warp
#pragma unroll
        for (int jj = 0; jj < 8; jj++)
            atomicAdd(&pooledS[8 * tx + jj], pool[jj]);
    }
    __syncthreads();

    // ---------------- final fc: out[b] = relu(pooled) @ fc_w + fc_b ----------------
    if (tid < C_OUT) {
        float s = __ldg(fc_b + tid);
#pragma unroll 8
        for (int h = 0; h < H_DIM; h++)
            s = fmaf(fmaxf(pooledS[h], 0.f), __ldg(fc_w + h * C_OUT + tid), s);
        out[b * C_OUT + tid] = s;
    }
}

// ---------------------------------------------------------------------------
extern "C" void kernel_launch(void* const* d_in, const int* in_sizes, int n_in,
                              void* d_out, int out_size) {
    const float* x      = (const float*)d_in[0];
    const float* edge_w = (const float*)d_in[1];
    const float* lin_w  = (const float*)d_in[2];
    const float* lin_b  = (const float*)d_in[3];
    const float* conv_w = (const float*)d_in[4];
    const float* conv_b = (const float*)d_in[5];
    const float* fc_w   = (const float*)d_in[6];
    const float* fc_b   = (const float*)d_in[7];
    float* out = (float*)d_out;

    const int smem_bytes =
        (F_DIM * X_STRIDE + N_NODES * Y_STRIDE + H_DIM) * (int)sizeof(float); // 102,912 B

    cudaFuncSetAttribute(fused_kernel,
                         cudaFuncAttributeMaxDynamicSharedMemorySize, smem_bytes);

    build_Ahat<<<N_NODES, 128>>>(edge_w);
    build_A2<<<N_NODES, 128>>>();
    fused_kernel<<<BATCH, 256, smem_bytes>>>(x, lin_w, lin_b, conv_w, conv_b,
                                             fc_w, fc_b, out);
}

// round 7
// speedup vs baseline: 5.3259x; 5.3259x over previous
#include <cuda_runtime.h>
#include <cuda_bf16.h>
#include <cstdint>
#include <math.h>

#define N_NODES 128
#define F_DIM   128
#define H_DIM   64
#define C_OUT   40
#define BATCH   4096

// ===========================================================================
// Device globals (prep kernels fill these each launch)
// ===========================================================================
__device__ __align__(16) float g_Ahat[N_NODES * N_NODES];
__device__                float g_deg[N_NODES];
__device__ __align__(16) float g_A2[N_NODES * N_NODES];
// A2 in mma A-fragment layout: [p(2)][w(8)][s(8)][lane(32)] uint4 (a0..a3)
__device__ __align__(16) uint4 g_A2frag[4096];
// W in mma B-fragment layout: [s(8)][p(2)][j(4)][lane(32)] uint4 (b0,b1 x 2 ntiles)
__device__ __align__(16) uint4 g_Wfrag[2048];

// ===========================================================================
// Helpers
// ===========================================================================
__device__ __forceinline__ unsigned smem_u32(const void* p) {
    unsigned a;
    asm("{ .reg .u64 t; cvta.to.shared.u64 t, %1; cvt.u32.u64 %0, t; }"
        : "=r"(a) : "l"(p));
    return a;
}

// pack two floats as bf16 pair; p=0 -> hi parts, p=1 -> lo residual parts
__device__ __forceinline__ unsigned bsplit_pack(float v0, float v1, int p) {
    __nv_bfloat16 h0 = __float2bfloat16(v0);
    __nv_bfloat16 h1 = __float2bfloat16(v1);
    if (p) {
        h0 = __float2bfloat16(v0 - __bfloat162float(h0));
        h1 = __float2bfloat16(v1 - __bfloat162float(h1));
    }
    return (unsigned)__bfloat16_as_ushort(h0) |
           ((unsigned)__bfloat16_as_ushort(h1) << 16);
}

__device__ __forceinline__ void mma_bf16(float* d, const unsigned* a,
                                         unsigned b0, unsigned b1) {
    asm volatile(
        "mma.sync.aligned.m16n8k16.row.col.f32.bf16.bf16.f32 "
        "{%0,%1,%2,%3}, {%4,%5,%6,%7}, {%8,%9}, {%0,%1,%2,%3};"
        : "+f"(d[0]), "+f"(d[1]), "+f"(d[2]), "+f"(d[3])
        : "r"(a[0]), "r"(a[1]), "r"(a[2]), "r"(a[3]), "r"(b0), "r"(b1));
}

#define LDM_X4(r, addr) \
    asm volatile("ldmatrix.sync.aligned.m8n8.x4.shared.b16 {%0,%1,%2,%3}, [%4];" \
        : "=r"((r)[0]), "=r"((r)[1]), "=r"((r)[2]), "=r"((r)[3]) : "r"(addr))
#define LDM_X4T(r, addr) \
    asm volatile("ldmatrix.sync.aligned.m8n8.x4.trans.shared.b16 {%0,%1,%2,%3}, [%4];" \
        : "=r"((r)[0]), "=r"((r)[1]), "=r"((r)[2]), "=r"((r)[3]) : "r"(addr))

// ===========================================================================
// Prep 1: Ahat = A_sym + I, degrees
// ===========================================================================
__global__ void build_Ahat(const float* __restrict__ edge_w) {
    __shared__ float red[4];
    int i = blockIdx.x, j = threadIdx.x;
    int a = i > j ? i : j;
    int b = i > j ? j : i;
    float v = edge_w[(a * (a + 1)) / 2 + b];
    if (i == j) v += 1.0f;
    g_Ahat[i * N_NODES + j] = v;
    float s = v;
#pragma unroll
    for (int o = 16; o > 0; o >>= 1) s += __shfl_xor_sync(0xffffffffu, s, o);
    if ((j & 31) == 0) red[j >> 5] = s;
    __syncthreads();
    if (j == 0) g_deg[i] = red[0] + red[1] + red[2] + red[3];
}

// ===========================================================================
// Prep 2: A2 = (D^-1/2 Ahat D^-1/2)^2 (fp32)
// ===========================================================================
__global__ void build_A2() {
    __shared__ float rowi[N_NODES];
    __shared__ float dinvS[N_NODES];
    int i = blockIdx.x, j = threadIdx.x;
    float dg = g_deg[j];
    float dj = (dg > 0.f) ? (1.0f / sqrtf(dg)) : 0.0f;
    dinvS[j] = dj;
    rowi[j] = g_Ahat[i * N_NODES + j] * dj * dj;
    __syncthreads();
    float s = 0.f;
    for (int k = 0; k < N_NODES; k++)
        s = fmaf(rowi[k], g_Ahat[k * N_NODES + j], s);
    g_A2[i * N_NODES + j] = s * dinvS[i] * dinvS[j];
}

// ===========================================================================
// Prep 3: A2 -> mma A-fragment layout (bf16 hi/lo). 4096 uint4.
// idx: l=idx&31, s=(idx>>5)&7, w=(idx>>8)&7, p=idx>>11
// a0=(r0,k0,k0+1) a1=(r0+8,..) a2=(r0,k0+8..) a3=(r0+8,k0+8..)
// ===========================================================================
__global__ void build_A2frag() {
    int idx = blockIdx.x * 256 + threadIdx.x;
    int l = idx & 31, s = (idx >> 5) & 7, w = (idx >> 8) & 7, p = idx >> 11;
    int r0 = 16 * w + (l >> 2);
    int k0 = 16 * s + 2 * (l & 3);
    const float* A = g_A2;
    uint4 r;
    r.x = bsplit_pack(A[r0 * 128 + k0],           A[r0 * 128 + k0 + 1],           p);
    r.y = bsplit_pack(A[(r0 + 8) * 128 + k0],     A[(r0 + 8) * 128 + k0 + 1],     p);
    r.z = bsplit_pack(A[r0 * 128 + k0 + 8],       A[r0 * 128 + k0 + 9],           p);
    r.w = bsplit_pack(A[(r0 + 8) * 128 + k0 + 8], A[(r0 + 8) * 128 + k0 + 9],     p);
    g_A2frag[idx] = r;
}

// ===========================================================================
// Prep 4: lin_w -> mma B-fragment layout (bf16 hi/lo). 2048 uint4.
// idx: l=idx&31, j=(idx>>5)&3, p=(idx>>7)&1, s=idx>>8
// ntiles t0=2j, t1=2j+1; b0: k=k0,k0+1 @ n; b1: k+8
// ===========================================================================
__global__ void build_Wfrag(const float* __restrict__ lin_w) {
    int idx = blockIdx.x * 256 + threadIdx.x;
    int l = idx & 31, j = (idx >> 5) & 3, p = (idx >> 7) & 1, s = idx >> 8;
    int n0 = 16 * j + (l >> 2);
    int n1 = n0 + 8;
    int k0 = 16 * s + 2 * (l & 3);
    const float* W = lin_w;
    uint4 r;
    r.x = bsplit_pack(W[k0 * 64 + n0],       W[(k0 + 1) * 64 + n0], p);
    r.y = bsplit_pack(W[(k0 + 8) * 64 + n0], W[(k0 + 9) * 64 + n0], p);
    r.z = bsplit_pack(W[k0 * 64 + n1],       W[(k0 + 1) * 64 + n1], p);
    r.w = bsplit_pack(W[(k0 + 8) * 64 + n1], W[(k0 + 9) * 64 + n1], p);
    g_Wfrag[idx] = r;
}

// ===========================================================================
// Fused kernel: 1 batch/CTA, 256 threads, 2 CTAs/SM.
// SMEM map (bytes):
//   Xhi [128][136] bf16 @0        (34816)  row stride 272B (16B-mult)
//   Xlo               @34816      (34816)
//   YW region         @69632      (36864): W-frags (32KB) during GEMM1,
//                                  then Yhi[128][72]bf16 (18432) + Ylo (18432)
//   pool/lb/cw        @106496     (1024): pool[64], lbS[64], cwS[128]
// ===========================================================================
#define SM_XLO   34816
#define SM_YW    69632
#define SM_POOL  106496
#define SM_TOTAL 107520
#define XSTRIDE  272
#define YSTRIDE  144

__global__ void __launch_bounds__(256, 2) fused_mma(
    const float* __restrict__ x,
    const float* __restrict__ lin_b,
    const float* __restrict__ conv_w, const float* __restrict__ conv_b,
    const float* __restrict__ fc_w, const float* __restrict__ fc_b,
    float* __restrict__ out)
{
    extern __shared__ char sm[];
    const unsigned smb = smem_u32(sm);
    const int tid = threadIdx.x, wid = tid >> 5, lane = tid & 31;
    const int b = blockIdx.x;

    float* pool = (float*)(sm + SM_POOL);
    float* lbS  = pool + 64;
    float* cwS  = pool + 128;
    if (tid < 64) { pool[tid] = __ldg(conv_b); lbS[tid] = __ldg(lin_b + tid); }
    if (tid < 128) cwS[tid] = __ldg(conv_w + tid);

    // ---- stage X (bf16 hi/lo split) + W fragments into smem ----
    {
        const float4* X4 = (const float4*)(x + (size_t)b * (N_NODES * F_DIM));
        char* Xhi = sm;
        char* Xlo = sm + SM_XLO;
#pragma unroll
        for (int i = 0; i < 16; i++) {
            int idx = tid + i * 256;
            float4 v = X4[idx];
            int n = idx >> 5, f4 = idx & 31;
            __nv_bfloat16 h0 = __float2bfloat16(v.x), h1 = __float2bfloat16(v.y);
            __nv_bfloat16 h2 = __float2bfloat16(v.z), h3 = __float2bfloat16(v.w);
            unsigned hw0 = (unsigned)__bfloat16_as_ushort(h0) |
                           ((unsigned)__bfloat16_as_ushort(h1) << 16);
            unsigned hw1 = (unsigned)__bfloat16_as_ushort(h2) |
                           ((unsigned)__bfloat16_as_ushort(h3) << 16);
            __nv_bfloat16 l0 = __float2bfloat16(v.x - __bfloat162float(h0));
            __nv_bfloat16 l1 = __float2bfloat16(v.y - __bfloat162float(h1));
            __nv_bfloat16 l2 = __float2bfloat16(v.z - __bfloat162float(h2));
            __nv_bfloat16 l3 = __float2bfloat16(v.w - __bfloat162float(h3));
            unsigned lw0 = (unsigned)__bfloat16_as_ushort(l0) |
                           ((unsigned)__bfloat16_as_ushort(l1) << 16);
            unsigned lw1 = (unsigned)__bfloat16_as_ushort(l2) |
                           ((unsigned)__bfloat16_as_ushort(l3) << 16);
            *(uint2*)(Xhi + n * XSTRIDE + f4 * 8) = make_uint2(hw0, hw1);
            *(uint2*)(Xlo + n * XSTRIDE + f4 * 8) = make_uint2(lw0, lw1);
        }
        uint4* WFs = (uint4*)(sm + SM_YW);
#pragma unroll
        for (int i = 0; i < 8; i++) WFs[tid + i * 256] = g_Wfrag[tid + i * 256];
    }
    __syncthreads();

    // ---- GEMM1: Y = X @ W  (3 split phases: hh, lh, hl) ----
    float acc[8][4];
#pragma unroll
    for (int t = 0; t < 8; t++)
#pragma unroll
        for (int q = 0; q < 4; q++) acc[t][q] = 0.f;

    {
        const uint4* WFs = (const uint4*)(sm + SM_YW);
        unsigned axh = smb + (16 * wid + (lane & 15)) * XSTRIDE + (lane >> 4) * 16;
        unsigned axl = axh + SM_XLO;
#pragma unroll
        for (int s = 0; s < 8; s++) {
            unsigned Ah[4], Al[4];
            LDM_X4(Ah, axh + s * 32);
            LDM_X4(Al, axl + s * 32);
            uint4 Bh[4], Bl[4];
#pragma unroll
            for (int j = 0; j < 4; j++) {
                Bh[j] = WFs[(8 * s + j) * 32 + lane];
                Bl[j] = WFs[(8 * s + 4 + j) * 32 + lane];
            }
#pragma unroll
            for (int j = 0; j < 4; j++) {
                mma_bf16(acc[2 * j],     Ah, Bh[j].x, Bh[j].y);
                mma_bf16(acc[2 * j + 1], Ah, Bh[j].z, Bh[j].w);
            }
#pragma unroll
            for (int j = 0; j < 4; j++) {
                mma_bf16(acc[2 * j],     Al, Bh[j].x, Bh[j].y);
                mma_bf16(acc[2 * j + 1], Al, Bh[j].z, Bh[j].w);
            }
#pragma unroll
            for (int j = 0; j < 4; j++) {
                mma_bf16(acc[2 * j],     Ah, Bl[j].x, Bl[j].y);
                mma_bf16(acc[2 * j + 1], Ah, Bl[j].z, Bl[j].w);
            }
        }
    }
    __syncthreads();   // all warps done reading W-frags; Y region reusable

    // ---- store Y split to smem ([node j][h] row-major, bf16) ----
    {
        char* Yhi = sm + SM_YW;
        char* Ylo = Yhi + 18432;
        int r0 = 16 * wid + (lane >> 2), r1 = r0 + 8;
        int c0 = 2 * (lane & 3);
#pragma unroll
        for (int t = 0; t < 8; t++) {
            int cb = (8 * t + c0) * 2;
            *(unsigned*)(Yhi + r0 * YSTRIDE + cb) = bsplit_pack(acc[t][0], acc[t][1], 0);
            *(unsigned*)(Yhi + r1 * YSTRIDE + cb) = bsplit_pack(acc[t][2], acc[t][3], 0);
            *(unsigned*)(Ylo + r0 * YSTRIDE + cb) = bsplit_pack(acc[t][0], acc[t][1], 1);
            *(unsigned*)(Ylo + r1 * YSTRIDE + cb) = bsplit_pack(acc[t][2], acc[t][3], 1);
        }
    }
    __syncthreads();

    // ---- GEMM2: Z = A2 @ Y  (A2 frags from global/L2, Y via ldmatrix.trans) ----
    float acc2[8][4];
#pragma unroll
    for (int t = 0; t < 8; t++)
#pragma unroll
        for (int q = 0; q < 4; q++) acc2[t][q] = 0.f;

    {
        unsigned ayh = smb + SM_YW + (lane & 15) * YSTRIDE + (lane >> 4) * 16;
        unsigned ayl = ayh + 18432;
#pragma unroll
        for (int s = 0; s < 8; s++) {
            uint4 vh = g_A2frag[(wid * 8 + s) * 32 + lane];
            uint4 vl = g_A2frag[((8 + wid) * 8 + s) * 32 + lane];
            unsigned ah[4] = {vh.x, vh.y, vh.z, vh.w};
            unsigned al[4] = {vl.x, vl.y, vl.z, vl.w};
            unsigned Yh[4][4], Yl[4][4];
#pragma unroll
            for (int jp = 0; jp < 4; jp++) {
                LDM_X4T(Yh[jp], ayh + s * (16 * YSTRIDE) + jp * 32);
                LDM_X4T(Yl[jp], ayl + s * (16 * YSTRIDE) + jp * 32);
            }
#pragma unroll
            for (int jp = 0; jp < 4; jp++) {
                mma_bf16(acc2[2 * jp],     ah, Yh[jp][0], Yh[jp][1]);
                mma_bf16(acc2[2 * jp + 1], ah, Yh[jp][2], Yh[jp][3]);
            }
#pragma unroll
            for (int jp = 0; jp < 4; jp++) {
                mma_bf16(acc2[2 * jp],     al, Yh[jp][0], Yh[jp][1]);
                mma_bf16(acc2[2 * jp + 1], al, Yh[jp][2], Yh[jp][3]);
            }
#pragma unroll
            for (int jp = 0; jp < 4; jp++) {
                mma_bf16(acc2[2 * jp],     ah, Yl[jp][0], Yl[jp][1]);
                mma_bf16(acc2[2 * jp + 1], ah, Yl[jp][2], Yl[jp][3]);
            }
        }
    }

    // ---- epilogue: relu(Z + lin_b) * conv_w, pool over nodes ----
    {
        float cw0 = cwS[16 * wid + (lane >> 2)];
        float cw1 = cwS[16 * wid + (lane >> 2) + 8];
#pragma unroll
        for (int t = 0; t < 8; t++) {
            int c0 = 8 * t + 2 * (lane & 3);
            float b0v = lbS[c0], b1v = lbS[c0 + 1];
            float p0 = fmaxf(acc2[t][0] + b0v, 0.f) * cw0 +
                       fmaxf(acc2[t][2] + b0v, 0.f) * cw1;
            float p1 = fmaxf(acc2[t][1] + b1v, 0.f) * cw0 +
                       fmaxf(acc2[t][3] + b1v, 0.f) * cw1;
#pragma unroll
            for (int o = 4; o <= 16; o <<= 1) {
                p0 += __shfl_xor_sync(0xffffffffu, p0, o);
                p1 += __shfl_xor_sync(0xffffffffu, p1, o);
            }
            if (lane < 4) {
                atomicAdd(&pool[c0], p0);
                atomicAdd(&pool[c0 + 1], p1);
            }
        }
    }
    __syncthreads();
    if (tid < 64) pool[tid] = fmaxf(pool[tid], 0.f);
    __syncthreads();

    // ---- final fc ----
    if (tid < C_OUT) {
        float s = __ldg(fc_b + tid);
#pragma unroll 8
        for (int h = 0; h < H_DIM; h++)
            s = fmaf(pool[h], __ldg(fc_w + h * C_OUT + tid), s);
        out[b * C_OUT + tid] = s;
    }
}

// ===========================================================================
extern "C" void kernel_launch(void* const* d_in, const int* in_sizes, int n_in,
                              void* d_out, int out_size) {
    const float* x      = (const float*)d_in[0];
    const float* edge_w = (const float*)d_in[1];
    const float* lin_w  = (const float*)d_in[2];
    const float* lin_b  = (const float*)d_in[3];
    const float* conv_w = (const float*)d_in[4];
    const float* conv_b = (const float*)d_in[5];
    const float* fc_w   = (const float*)d_in[6];
    const float* fc_b   = (const float*)d_in[7];
    float* out = (float*)d_out;

    cudaFuncSetAttribute(fused_mma, cudaFuncAttributeMaxDynamicSharedMemorySize,
                         SM_TOTAL);

    build_Ahat<<<N_NODES, 128>>>(edge_w);
    build_A2<<<N_NODES, 128>>>();
    build_A2frag<<<16, 256>>>();
    build_Wfrag<<<8, 256>>>(lin_w);
    fused_mma<<<BATCH, 256, SM_TOTAL>>>(x, lin_b, conv_w, conv_b, fc_w, fc_b, out);
}

// round 8
// speedup vs baseline: 5.9730x; 1.1215x over previous
#include <cuda_runtime.h>
#include <cuda_bf16.h>
#include <cstdint>
#include <math.h>

#define N_NODES 128
#define F_DIM   128
#define H_DIM   64
#define C_OUT   40
#define BATCH   4096

// ===========================================================================
// Device globals (prep kernels fill these each launch)
// ===========================================================================
__device__ __align__(16) float g_Ahat[N_NODES * N_NODES];
__device__                float g_deg[N_NODES];
__device__ __align__(16) float g_A2[N_NODES * N_NODES];
// A2 in mma A-fragment layout: [p(2)][mtile(8)][s(8)][lane(32)] uint4
__device__ __align__(16) uint4 g_A2frag[4096];
// W in mma B-fragment layout: [s(8)][p(2)][j(4)][lane(32)] uint4
__device__ __align__(16) uint4 g_Wfrag[2048];

// ===========================================================================
// Helpers
// ===========================================================================
__device__ __forceinline__ unsigned smem_u32(const void* p) {
    unsigned a;
    asm("{ .reg .u64 t; cvta.to.shared.u64 t, %1; cvt.u32.u64 %0, t; }"
        : "=r"(a) : "l"(p));
    return a;
}

// packed bf16x2 convert: low half <- v0, high half <- v1
__device__ __forceinline__ unsigned cvt_bf2(float v0, float v1) {
    unsigned r;
    asm("cvt.rn.bf16x2.f32 %0, %1, %2;" : "=r"(r) : "f"(v1), "f"(v0));
    return r;
}
// split two floats into hi bf16x2 + residual-lo bf16x2 (6 ops)
__device__ __forceinline__ void split2(float v0, float v1,
                                       unsigned& hi, unsigned& lo) {
    hi = cvt_bf2(v0, v1);
    float h0 = __uint_as_float(hi << 16);
    float h1 = __uint_as_float(hi & 0xffff0000u);
    lo = cvt_bf2(v0 - h0, v1 - h1);
}
// prep-side pack (p=0 hi, p=1 lo)
__device__ __forceinline__ unsigned bsplit_pack(float v0, float v1, int p) {
    __nv_bfloat16 h0 = __float2bfloat16(v0);
    __nv_bfloat16 h1 = __float2bfloat16(v1);
    if (p) {
        h0 = __float2bfloat16(v0 - __bfloat162float(h0));
        h1 = __float2bfloat16(v1 - __bfloat162float(h1));
    }
    return (unsigned)__bfloat16_as_ushort(h0) |
           ((unsigned)__bfloat16_as_ushort(h1) << 16);
}

__device__ __forceinline__ void mma_bf16(float* d, const unsigned* a,
                                         unsigned b0, unsigned b1) {
    asm volatile(
        "mma.sync.aligned.m16n8k16.row.col.f32.bf16.bf16.f32 "
        "{%0,%1,%2,%3}, {%4,%5,%6,%7}, {%8,%9}, {%0,%1,%2,%3};"
        : "+f"(d[0]), "+f"(d[1]), "+f"(d[2]), "+f"(d[3])
        : "r"(a[0]), "r"(a[1]), "r"(a[2]), "r"(a[3]), "r"(b0), "r"(b1));
}

#define LDM_X4(r, addr) \
    asm volatile("ldmatrix.sync.aligned.m8n8.x4.shared.b16 {%0,%1,%2,%3}, [%4];" \
        : "=r"((r)[0]), "=r"((r)[1]), "=r"((r)[2]), "=r"((r)[3]) : "r"(addr))
#define LDM_X4T(r, addr) \
    asm volatile("ldmatrix.sync.aligned.m8n8.x4.trans.shared.b16 {%0,%1,%2,%3}, [%4];" \
        : "=r"((r)[0]), "=r"((r)[1]), "=r"((r)[2]), "=r"((r)[3]) : "r"(addr))

// ===========================================================================
// Prep 1: Ahat = A_sym + I, degrees
// ===========================================================================
__global__ void build_Ahat(const float* __restrict__ edge_w) {
    __shared__ float red[4];
    int i = blockIdx.x, j = threadIdx.x;
    int a = i > j ? i : j;
    int b = i > j ? j : i;
    float v = edge_w[(a * (a + 1)) / 2 + b];
    if (i == j) v += 1.0f;
    g_Ahat[i * N_NODES + j] = v;
    float s = v;
#pragma unroll
    for (int o = 16; o > 0; o >>= 1) s += __shfl_xor_sync(0xffffffffu, s, o);
    if ((j & 31) == 0) red[j >> 5] = s;
    __syncthreads();
    if (j == 0) g_deg[i] = red[0] + red[1] + red[2] + red[3];
}

// ===========================================================================
// Prep 2: A2 = (D^-1/2 Ahat D^-1/2)^2 (fp32)
// ===========================================================================
__global__ void build_A2() {
    __shared__ float rowi[N_NODES];
    __shared__ float dinvS[N_NODES];
    int i = blockIdx.x, j = threadIdx.x;
    float dg = g_deg[j];
    float dj = (dg > 0.f) ? (1.0f / sqrtf(dg)) : 0.0f;
    dinvS[j] = dj;
    rowi[j] = g_Ahat[i * N_NODES + j] * dj * dj;
    __syncthreads();
    float s = 0.f;
    for (int k = 0; k < N_NODES; k++)
        s = fmaf(rowi[k], g_Ahat[k * N_NODES + j], s);
    g_A2[i * N_NODES + j] = s * dinvS[i] * dinvS[j];
}

// ===========================================================================
// Prep 3 (fused): A2 -> A-fragment layout; lin_w -> B-fragment layout.
// Blocks 0-15: A2frag (4096 uint4). Blocks 16-23: Wfrag (2048 uint4).
// ===========================================================================
__global__ void build_frags(const float* __restrict__ lin_w) {
    int bid = blockIdx.x;
    if (bid < 16) {
        int idx = bid * 256 + threadIdx.x;
        int l = idx & 31, s = (idx >> 5) & 7, w = (idx >> 8) & 7, p = idx >> 11;
        int r0 = 16 * w + (l >> 2);
        int k0 = 16 * s + 2 * (l & 3);
        const float* A = g_A2;
        uint4 r;
        r.x = bsplit_pack(A[r0 * 128 + k0],           A[r0 * 128 + k0 + 1],       p);
        r.y = bsplit_pack(A[(r0 + 8) * 128 + k0],     A[(r0 + 8) * 128 + k0 + 1], p);
        r.z = bsplit_pack(A[r0 * 128 + k0 + 8],       A[r0 * 128 + k0 + 9],       p);
        r.w = bsplit_pack(A[(r0 + 8) * 128 + k0 + 8], A[(r0 + 8) * 128 + k0 + 9], p);
        g_A2frag[idx] = r;
    } else {
        int idx = (bid - 16) * 256 + threadIdx.x;
        int l = idx & 31, j = (idx >> 5) & 3, p = (idx >> 7) & 1, s = idx >> 8;
        int n0 = 16 * j + (l >> 2);
        int n1 = n0 + 8;
        int k0 = 16 * s + 2 * (l & 3);
        const float* W = lin_w;
        uint4 r;
        r.x = bsplit_pack(W[k0 * 64 + n0],       W[(k0 + 1) * 64 + n0], p);
        r.y = bsplit_pack(W[(k0 + 8) * 64 + n0], W[(k0 + 9) * 64 + n0], p);
        r.z = bsplit_pack(W[k0 * 64 + n1],       W[(k0 + 1) * 64 + n1], p);
        r.w = bsplit_pack(W[(k0 + 8) * 64 + n1], W[(k0 + 9) * 64 + n1], p);
        g_Wfrag[idx] = r;
    }
}

// ===========================================================================
// Fused kernel: 1 batch/CTA, 256 threads, 2 CTAs/SM.
// 2-D warp grid: wM = wid&3 (rows 32*wM..+31), wN = wid>>2 (cols 32*wN..+31).
// Halves B-fragment smem duplication vs 1-D (8x -> 4x).
// SMEM map: Xhi [128][136]bf16 @0 (34816) | Xlo @34816 |
//   YW @69632 (36864): W-frags (32KB) during GEMM1, then Yhi/Ylo [128][72]bf16
//   pool/lb/cw @106496 (1024)
// ===========================================================================
#define SM_XLO   34816
#define SM_YW    69632
#define SM_POOL  106496
#define SM_TOTAL 107520
#define XSTRIDE  272
#define YSTRIDE  144

__global__ void __launch_bounds__(256, 2) fused_mma(
    const float* __restrict__ x,
    const float* __restrict__ lin_b,
    const float* __restrict__ conv_w, const float* __restrict__ conv_b,
    const float* __restrict__ fc_w, const float* __restrict__ fc_b,
    float* __restrict__ out)
{
    extern __shared__ char sm[];
    const unsigned smb = smem_u32(sm);
    const int tid = threadIdx.x, wid = tid >> 5, lane = tid & 31;
    const int wM = wid & 3, wN = wid >> 2;
    const int b = blockIdx.x;

    float* pool = (float*)(sm + SM_POOL);
    float* lbS  = pool + 64;
    float* cwS  = pool + 128;
    if (tid < 64) { pool[tid] = __ldg(conv_b); lbS[tid] = __ldg(lin_b + tid); }
    if (tid < 128) cwS[tid] = __ldg(conv_w + tid);

    // ---- stage X (bf16 hi/lo split) + W fragments into smem ----
    {
        const float4* X4 = (const float4*)(x + (size_t)b * (N_NODES * F_DIM));
        char* Xhi = sm;
        char* Xlo = sm + SM_XLO;
#pragma unroll
        for (int i = 0; i < 16; i++) {
            int idx = tid + i * 256;
            float4 v = X4[idx];
            int n = idx >> 5, f4 = idx & 31;
            unsigned hw0, lw0, hw1, lw1;
            split2(v.x, v.y, hw0, lw0);
            split2(v.z, v.w, hw1, lw1);
            *(uint2*)(Xhi + n * XSTRIDE + f4 * 8) = make_uint2(hw0, hw1);
            *(uint2*)(Xlo + n * XSTRIDE + f4 * 8) = make_uint2(lw0, lw1);
        }
        uint4* WFs = (uint4*)(sm + SM_YW);
#pragma unroll
        for (int i = 0; i < 8; i++) WFs[tid + i * 256] = g_Wfrag[tid + i * 256];
    }
    __syncthreads();

    // ---- GEMM1: Y = X @ W  (3 split phases: hh, lh, hl) ----
    float acc[2][4][4];
#pragma unroll
    for (int m = 0; m < 2; m++)
#pragma unroll
        for (int t = 0; t < 4; t++)
#pragma unroll
            for (int q = 0; q < 4; q++) acc[m][t][q] = 0.f;

    {
        const uint4* WFs = (const uint4*)(sm + SM_YW);
        unsigned axh0 = smb + (32 * wM + (lane & 15)) * XSTRIDE + (lane >> 4) * 16;
        unsigned axh1 = axh0 + 16 * XSTRIDE;
        unsigned axl0 = axh0 + SM_XLO;
        unsigned axl1 = axh1 + SM_XLO;
#pragma unroll
        for (int s = 0; s < 8; s++) {
            unsigned Ah0[4], Ah1[4], Al0[4], Al1[4];
            LDM_X4(Ah0, axh0 + s * 32);
            LDM_X4(Ah1, axh1 + s * 32);
            LDM_X4(Al0, axl0 + s * 32);
            LDM_X4(Al1, axl1 + s * 32);
            uint4 Bh0 = WFs[(8 * s + 2 * wN) * 32 + lane];
            uint4 Bh1 = WFs[(8 * s + 2 * wN + 1) * 32 + lane];
            uint4 Bl0 = WFs[(8 * s + 4 + 2 * wN) * 32 + lane];
            uint4 Bl1 = WFs[(8 * s + 4 + 2 * wN + 1) * 32 + lane];
            // hi*hi
            mma_bf16(acc[0][0], Ah0, Bh0.x, Bh0.y);
            mma_bf16(acc[0][1], Ah0, Bh0.z, Bh0.w);
            mma_bf16(acc[0][2], Ah0, Bh1.x, Bh1.y);
            mma_bf16(acc[0][3], Ah0, Bh1.z, Bh1.w);
            mma_bf16(acc[1][0], Ah1, Bh0.x, Bh0.y);
            mma_bf16(acc[1][1], Ah1, Bh0.z, Bh0.w);
            mma_bf16(acc[1][2], Ah1, Bh1.x, Bh1.y);
            mma_bf16(acc[1][3], Ah1, Bh1.z, Bh1.w);
            // lo*hi
            mma_bf16(acc[0][0], Al0, Bh0.x, Bh0.y);
            mma_bf16(acc[0][1], Al0, Bh0.z, Bh0.w);
            mma_bf16(acc[0][2], Al0, Bh1.x, Bh1.y);
            mma_bf16(acc[0][3], Al0, Bh1.z, Bh1.w);
            mma_bf16(acc[1][0], Al1, Bh0.x, Bh0.y);
            mma_bf16(acc[1][1], Al1, Bh0.z, Bh0.w);
            mma_bf16(acc[1][2], Al1, Bh1.x, Bh1.y);
            mma_bf16(acc[1][3], Al1, Bh1.z, Bh1.w);
            // hi*lo
            mma_bf16(acc[0][0], Ah0, Bl0.x, Bl0.y);
            mma_bf16(acc[0][1], Ah0, Bl0.z, Bl0.w);
            mma_bf16(acc[0][2], Ah0, Bl1.x, Bl1.y);
            mma_bf16(acc[0][3], Ah0, Bl1.z, Bl1.w);
            mma_bf16(acc[1][0], Ah1, Bl0.x, Bl0.y);
            mma_bf16(acc[1][1], Ah1, Bl0.z, Bl0.w);
            mma_bf16(acc[1][2], Ah1, Bl1.x, Bl1.y);
            mma_bf16(acc[1][3], Ah1, Bl1.z, Bl1.w);
        }
    }
    __syncthreads();   // all warps done reading W-frags; region reusable for Y

    // ---- store Y split to smem ([node][h] row-major, bf16) ----
    {
        char* Yhi = sm + SM_YW;
        char* Ylo = Yhi + 18432;
        int r0 = 32 * wM + (lane >> 2);
        int c0 = 32 * wN + 2 * (lane & 3);
#pragma unroll
        for (int m = 0; m < 2; m++) {
            int r = r0 + 16 * m;
#pragma unroll
            for (int t = 0; t < 4; t++) {
                const float* a = acc[m][t];
                int cb = (c0 + 8 * t) * 2;
                unsigned h0, l0, h1, l1;
                split2(a[0], a[1], h0, l0);
                split2(a[2], a[3], h1, l1);
                *(unsigned*)(Yhi + r * YSTRIDE + cb)       = h0;
                *(unsigned*)(Yhi + (r + 8) * YSTRIDE + cb) = h1;
                *(unsigned*)(Ylo + r * YSTRIDE + cb)       = l0;
                *(unsigned*)(Ylo + (r + 8) * YSTRIDE + cb) = l1;
            }
        }
    }
    __syncthreads();

    // ---- GEMM2: Z = A2 @ Y  (A2 frags from L2, Y via ldmatrix.trans) ----
    float acc2[2][4][4];
#pragma unroll
    for (int m = 0; m < 2; m++)
#pragma unroll
        for (int t = 0; t < 4; t++)
#pragma unroll
            for (int q = 0; q < 4; q++) acc2[m][t][q] = 0.f;

    {
        unsigned ayh = smb + SM_YW + (lane & 15) * YSTRIDE + (lane >> 4) * 16;
        unsigned ayl = ayh + 18432;
#pragma unroll
        for (int s = 0; s < 8; s++) {
            uint4 vh0 = g_A2frag[((2 * wM) * 8 + s) * 32 + lane];
            uint4 vh1 = g_A2frag[((2 * wM + 1) * 8 + s) * 32 + lane];
            uint4 vl0 = g_A2frag[2048 + ((2 * wM) * 8 + s) * 32 + lane];
            uint4 vl1 = g_A2frag[2048 + ((2 * wM + 1) * 8 + s) * 32 + lane];
            unsigned ah0[4] = {vh0.x, vh0.y, vh0.z, vh0.w};
            unsigned ah1[4] = {vh1.x, vh1.y, vh1.z, vh1.w};
            unsigned al0[4] = {vl0.x, vl0.y, vl0.z, vl0.w};
            unsigned al1[4] = {vl1.x, vl1.y, vl1.z, vl1.w};
            unsigned Yh0[4], Yh1[4], Yl0[4], Yl1[4];
            unsigned yb = s * (16 * YSTRIDE);
            LDM_X4T(Yh0, ayh + yb + (2 * wN) * 32);
            LDM_X4T(Yh1, ayh + yb + (2 * wN + 1) * 32);
            LDM_X4T(Yl0, ayl + yb + (2 * wN) * 32);
            LDM_X4T(Yl1, ayl + yb + (2 * wN + 1) * 32);
            // hi*hi
            mma_bf16(acc2[0][0], ah0, Yh0[0], Yh0[1]);
            mma_bf16(acc2[0][1], ah0, Yh0[2], Yh0[3]);
            mma_bf16(acc2[0][2], ah0, Yh1[0], Yh1[1]);
            mma_bf16(acc2[0][3], ah0, Yh1[2], Yh1[3]);
            mma_bf16(acc2[1][0], ah1, Yh0[0], Yh0[1]);
            mma_bf16(acc2[1][1], ah1, Yh0[2], Yh0[3]);
            mma_bf16(acc2[1][2], ah1, Yh1[0], Yh1[1]);
            mma_bf16(acc2[1][3], ah1, Yh1[2], Yh1[3]);
            // lo*hi
            mma_bf16(acc2[0][0], al0, Yh0[0], Yh0[1]);
            mma_bf16(acc2[0][1], al0, Yh0[2], Yh0[3]);
            mma_bf16(acc2[0][2], al0, Yh1[0], Yh1[1]);
            mma_bf16(acc2[0][3], al0, Yh1[2], Yh1[3]);
            mma_bf16(acc2[1][0], al1, Yh0[0], Yh0[1]);
            mma_bf16(acc2[1][1], al1, Yh0[2], Yh0[3]);
            mma_bf16(acc2[1][2], al1, Yh1[0], Yh1[1]);
            mma_bf16(acc2[1][3], al1, Yh1[2], Yh1[3]);
            // hi*lo
            mma_bf16(acc2[0][0], ah0, Yl0[0], Yl0[1]);
            mma_bf16(acc2[0][1], ah0, Yl0[2], Yl0[3]);
            mma_bf16(acc2[0][2], ah0, Yl1[0], Yl1[1]);
            mma_bf16(acc2[0][3], ah0, Yl1[2], Yl1[3]);
            mma_bf16(acc2[1][0], ah1, Yl0[0], Yl0[1]);
            mma_bf16(acc2[1][1], ah1, Yl0[2], Yl0[3]);
            mma_bf16(acc2[1][2], ah1, Yl1[0], Yl1[1]);
            mma_bf16(acc2[1][3], ah1, Yl1[2], Yl1[3]);
        }
    }

    // ---- epilogue: relu(Z + lin_b) * conv_w, pool over nodes ----
    {
        int rb = 32 * wM + (lane >> 2);
        float cwA = cwS[rb],      cwB = cwS[rb + 8];
        float cwC = cwS[rb + 16], cwD = cwS[rb + 24];
#pragma unroll
        for (int t = 0; t < 4; t++) {
            int c0 = 32 * wN + 8 * t + 2 * (lane & 3);
            float b0v = lbS[c0], b1v = lbS[c0 + 1];
            float p0 = fmaxf(acc2[0][t][0] + b0v, 0.f) * cwA +
                       fmaxf(acc2[0][t][2] + b0v, 0.f) * cwB +
                       fmaxf(acc2[1][t][0] + b0v, 0.f) * cwC +
                       fmaxf(acc2[1][t][2] + b0v, 0.f) * cwD;
            float p1 = fmaxf(acc2[0][t][1] + b1v, 0.f) * cwA +
                       fmaxf(acc2[0][t][3] + b1v, 0.f) * cwB +
                       fmaxf(acc2[1][t][1] + b1v, 0.f) * cwC +
                       fmaxf(acc2[1][t][3] + b1v, 0.f) * cwD;
#pragma unroll
            for (int o = 4; o <= 16; o <<= 1) {
                p0 += __shfl_xor_sync(0xffffffffu, p0, o);
                p1 += __shfl_xor_sync(0xffffffffu, p1, o);
            }
            if (lane < 4) {
                atomicAdd(&pool[c0], p0);
                atomicAdd(&pool[c0 + 1], p1);
            }
        }
    }
    __syncthreads();
    if (tid < 64) pool[tid] = fmaxf(pool[tid], 0.f);
    __syncthreads();

    // ---- final fc ----
    if (tid < C_OUT) {
        float s = __ldg(fc_b + tid);
#pragma unroll 8
        for (int h = 0; h < H_DIM; h++)
            s = fmaf(pool[h], __ldg(fc_w + h * C_OUT + tid), s);
        out[b * C_OUT + tid] = s;
    }
}

// ===========================================================================
extern "C" void kernel_launch(void* const* d_in, const int* in_sizes, int n_in,
                              void* d_out, int out_size) {
    const float* x      = (const float*)d_in[0];
    const float* edge_w = (const float*)d_in[1];
    const float* lin_w  = (const float*)d_in[2];
    const float* lin_b  = (const float*)d_in[3];
    const float* conv_w = (const float*)d_in[4];
    const float* conv_b = (const float*)d_in[5];
    const float* fc_w   = (const float*)d_in[6];
    const float* fc_b   = (const float*)d_in[7];
    float* out = (float*)d_out;

    cudaFuncSetAttribute(fused_mma, cudaFuncAttributeMaxDynamicSharedMemorySize,
                         SM_TOTAL);

    build_Ahat<<<N_NODES, 128>>>(edge_w);
    build_A2<<<N_NODES, 128>>>();
    build_frags<<<24, 256>>>(lin_w);
    fused_mma<<<BATCH, 256, SM_TOTAL>>>(x, lin_b, conv_w, conv_b, fc_w, fc_b, out);
}